// round 4
// baseline (speedup 1.0000x reference)
#include <cuda_runtime.h>
#include <cuda_bf16.h>

// Problem constants
#define BN 4096
#define N  98
#define C  96
#define H  3
#define HD 32
#define TC 288          // 3*C
#define NT 256          // threads per CTA
#define SCALE 0.17677669529663687f   // 1/sqrt(32)

// Shared-memory strides (in floats) chosen for bank-conflict avoidance +
// 8B alignment of float2/LDS.64 pair accesses (even strides where pairs used).
#define SX_LD 97        // odd: conflict-free column access; scalar-only
#define SQ_LD 290       // even (pair loads of v), %32==2 -> 2-way worst case
#define SA_LD 99        // odd: conflict-free; scalar-only
#define SK_LD 100       // even: kT pair loads aligned
#define SW_LD 34        // even: weight-tile pair loads aligned, 2-way write conflicts only

// Float offsets of regions inside dynamic smem (all even -> 8B aligned)
#define OFF_SX 0                       // 98*97 = 9506 -> pad 9508
#define OFF_SQ 9508                    // 98*290 = 28420
#define OFF_SA 37928                   // 98*99  = 9702
#define OFF_SK 47630                   // 32*100 = 3200
#define OFF_SW 50830                   // 96*34  = 3264
#define OFF_RI 54094                   // 98 -> pad to 54208
#define SMEM_FLOATS 54208
#define SMEM_BYTES (SMEM_FLOATS * 4)   // 216,832 B  (< 227KB limit)

typedef unsigned long long ull;

__device__ float g_bias[H * N * N];    // bias[h][n][m], precomputed once per launch

// ---- packed f32x2 helpers (Blackwell FFMA2 path: only reachable via PTX) ----
__device__ __forceinline__ ull pk2(float lo, float hi) {
    ull r; asm("mov.b64 %0,{%1,%2};" : "=l"(r) : "f"(lo), "f"(hi)); return r;
}
__device__ __forceinline__ void fm2(ull& d, ull a, ull b) {
    asm("fma.rn.f32x2 %0,%1,%2,%0;" : "+l"(d) : "l"(a), "l"(b));
}
__device__ __forceinline__ float2 upk2(ull v) {
    float2 r; asm("mov.b64 {%0,%1},%2;" : "=f"(r.x), "=f"(r.y) : "l"(v)); return r;
}

// ---- prep: g_bias[h*N*N + n*N + m] = bias_table[rel_index[n*N+m]*H + h] ----
__global__ void bias_prep(const float* __restrict__ table, const int* __restrict__ rel) {
    int i = blockIdx.x * blockDim.x + threadIdx.x;
    if (i < H * N * N) {
        int h = i / (N * N);
        int r = i - h * (N * N);
        g_bias[i] = table[rel[r] * H + h];
    }
}

// ---- main fused kernel: one CTA per window ----
__global__ void __launch_bounds__(NT, 1)
wa3d_main(const float* __restrict__ x,
          const float* __restrict__ qkv_w, const float* __restrict__ qkv_b,
          const float* __restrict__ proj_w, const float* __restrict__ proj_b,
          float* __restrict__ out)
{
    extern __shared__ float sm[];
    float* sx = sm + OFF_SX;   // x, later attention output [98][97]
    float* sq = sm + OFF_SQ;   // qkv [98][290] (cols: q 0..95, k 96..191, v 192..287)
    float* sa = sm + OFF_SA;   // scores / probs [98][99]
    float* sk = sm + OFF_SK;   // kT [32][100]
    float* sw = sm + OFF_SW;   // weight tile transposed [96][34]
    float* ri = sm + OFF_RI;   // row 1/sum [98]

    const int b   = blockIdx.x;
    const int tid = threadIdx.x;

    // ---- stage x[b] into smem (coalesced global reads) ----
    const float* xb = x + (size_t)b * (N * C);
    for (int i = tid; i < N * C; i += NT) {
        int r = i / C, c = i - r * C;
        sx[r * SX_LD + c] = xb[i];
    }
    __syncthreads();

    // common per-thread row mapping for GEMM1 / proj
    const int cg = tid >> 6;            // 0..3 : column group of 8 cols (4 pairs)
    const int rt = tid & 63;            // row 0..63
    const int r1 = rt + 64;
    const bool v1 = (r1 < N);

    // ==================== GEMM1: qkv = x @ qkv_w^T + qkv_b ====================
    {
        const float* a0p = sx + rt * SX_LD;
        const float* a1p = sx + (v1 ? r1 : rt) * SX_LD;
        for (int ot = 0; ot < TC / 32; ++ot) {
            // stage weight tile transposed: sw[c][j] = qkv_w[(ot*32+j)*C + c]
            for (int i = tid; i < 32 * C; i += NT) {
                int j = i / C, c = i - j * C;          // coalesced over c
                sw[c * SW_LD + j] = qkv_w[(ot * 32 + j) * C + c];
            }
            __syncthreads();

            ull acc[2][4];
            #pragma unroll
            for (int p = 0; p < 4; ++p) { acc[0][p] = 0ull; acc[1][p] = 0ull; }

            #pragma unroll 4
            for (int c = 0; c < C; ++c) {
                float a0s = a0p[c], a1s = a1p[c];
                ull a0 = pk2(a0s, a0s), a1 = pk2(a1s, a1s);
                const ull* wp = (const ull*)(sw + c * SW_LD + cg * 8);
                #pragma unroll
                for (int p = 0; p < 4; ++p) {
                    ull w = wp[p];
                    fm2(acc[0][p], a0, w);
                    fm2(acc[1][p], a1, w);
                }
            }

            int cbase = ot * 32 + cg * 8;
            #pragma unroll
            for (int p = 0; p < 4; ++p) {
                float2 bb = *(const float2*)(qkv_b + cbase + 2 * p);
                float2 u0 = upk2(acc[0][p]);
                sq[rt * SQ_LD + cbase + 2 * p]     = u0.x + bb.x;
                sq[rt * SQ_LD + cbase + 2 * p + 1] = u0.y + bb.y;
                if (v1) {
                    float2 u1 = upk2(acc[1][p]);
                    sq[r1 * SQ_LD + cbase + 2 * p]     = u1.x + bb.x;
                    sq[r1 * SQ_LD + cbase + 2 * p + 1] = u1.y + bb.y;
                }
            }
            __syncthreads();
        }
    }

    // ==================== attention per head ====================
    const int warp = tid >> 5, lane = tid & 31;
    for (int h = 0; h < H; ++h) {
        // ---- kT[d][m] = k[m][d] ----
        for (int i = tid; i < HD * N; i += NT) {
            int d = i / N, m = i - d * N;
            sk[d * SK_LD + m] = sq[m * SQ_LD + C + h * HD + d];
        }
        __syncthreads();

        // ---- scores: S[n][m] = scale * q.k + bias  (2x8 thread tiles) ----
        for (int t = tid; t < 49 * 13; t += NT) {
            int tn = t / 13, tm = t - tn * 13;
            int n0 = tn * 2, m0 = tm * 8;
            ull acc[2][4];
            #pragma unroll
            for (int p = 0; p < 4; ++p) { acc[0][p] = 0ull; acc[1][p] = 0ull; }

            const float* q0 = sq + n0 * SQ_LD + h * HD;
            const float* q1 = q0 + SQ_LD;                  // n0+1 <= 97 always
            #pragma unroll 8
            for (int d = 0; d < HD; ++d) {
                float q0s = q0[d], q1s = q1[d];
                ull qa = pk2(q0s, q0s), qb = pk2(q1s, q1s);
                const ull* kp = (const ull*)(sk + d * SK_LD + m0);
                #pragma unroll
                for (int p = 0; p < 4; ++p) {
                    ull kv = kp[p];
                    fm2(acc[0][p], qa, kv);
                    fm2(acc[1][p], qb, kv);
                }
            }
            const float* gb0 = g_bias + (h * N + n0) * N;
            #pragma unroll
            for (int p = 0; p < 4; ++p) {
                int m = m0 + 2 * p;
                float2 u0 = upk2(acc[0][p]), u1 = upk2(acc[1][p]);
                if (m < N) {
                    sa[n0 * SA_LD + m]       = u0.x * SCALE + gb0[m];
                    sa[(n0 + 1) * SA_LD + m] = u1.x * SCALE + gb0[N + m];
                }
                if (m + 1 < N) {
                    sa[n0 * SA_LD + m + 1]       = u0.y * SCALE + gb0[m + 1];
                    sa[(n0 + 1) * SA_LD + m + 1] = u1.y * SCALE + gb0[N + m + 1];
                }
            }
        }
        __syncthreads();

        // ---- softmax rows (warp per row, store exp; 1/sum folded into PV) ----
        // N=98 = 3*32 + 2: chunks at lane, lane+32, lane+64, and (lane<2) lane+96.
        for (int r = warp; r < N; r += 8) {
            float* row = sa + r * SA_LD;
            float v0 = row[lane];
            float va = row[lane + 32];
            float vb = row[lane + 64];                 // 64..95 < 98, always valid
            bool  g3 = (lane < 2);
            float vc = g3 ? row[lane + 96] : -1e30f;   // 96..97
            float mx = fmaxf(fmaxf(v0, va), fmaxf(vb, vc));
            #pragma unroll
            for (int s = 16; s; s >>= 1) mx = fmaxf(mx, __shfl_xor_sync(~0u, mx, s));
            float e0 = __expf(v0 - mx);
            float e1 = __expf(va - mx);
            float e2 = __expf(vb - mx);
            float e3 = g3 ? __expf(vc - mx) : 0.f;
            row[lane] = e0; row[lane + 32] = e1; row[lane + 64] = e2;
            if (g3) row[lane + 96] = e3;
            float s = e0 + e1 + e2 + e3;
            #pragma unroll
            for (int sh = 16; sh; sh >>= 1) s += __shfl_xor_sync(~0u, s, sh);
            if (lane == 0) ri[r] = 1.0f / s;
        }
        __syncthreads();

        // ---- PV: out[n][d] = (sum_m P v) * rinv[n]   (2x8 tiles, 196 tiles) ----
        for (int t = tid; t < 49 * 4; t += NT) {
            int tn = t >> 2, td = t & 3;
            int n0 = tn * 2, d0 = td * 8;
            ull acc[2][4];
            #pragma unroll
            for (int p = 0; p < 4; ++p) { acc[0][p] = 0ull; acc[1][p] = 0ull; }

            const float* p0 = sa + n0 * SA_LD;
            const float* p1 = p0 + SA_LD;
            const float* vb = sq + 2 * C + h * HD + d0;
            #pragma unroll 2
            for (int m = 0; m < N; ++m) {
                float pa = p0[m], pb = p1[m];
                ull A = pk2(pa, pa), Bp = pk2(pb, pb);
                const ull* vp = (const ull*)(vb + m * SQ_LD);
                #pragma unroll
                for (int p = 0; p < 4; ++p) {
                    ull vv = vp[p];
                    fm2(acc[0][p], A, vv);
                    fm2(acc[1][p], Bp, vv);
                }
            }
            float r0i = ri[n0], r1i = ri[n0 + 1];
            int colb = h * HD + d0;
            #pragma unroll
            for (int p = 0; p < 4; ++p) {
                float2 u0 = upk2(acc[0][p]), u1 = upk2(acc[1][p]);
                int col = colb + 2 * p;
                sx[n0 * SX_LD + col]           = u0.x * r0i;
                sx[n0 * SX_LD + col + 1]       = u0.y * r0i;
                sx[(n0 + 1) * SX_LD + col]     = u1.x * r1i;
                sx[(n0 + 1) * SX_LD + col + 1] = u1.y * r1i;
            }
        }
        __syncthreads();
    }

    // ==================== proj: out = attn_out @ proj_w^T + proj_b ====================
    {
        const float* o0p = sx + rt * SX_LD;
        const float* o1p = sx + (v1 ? r1 : rt) * SX_LD;
        float* ob = out + (size_t)b * (N * C);
        for (int ot = 0; ot < C / 32; ++ot) {
            for (int i = tid; i < 32 * C; i += NT) {
                int j = i / C, c = i - j * C;
                sw[c * SW_LD + j] = proj_w[(ot * 32 + j) * C + c];
            }
            __syncthreads();

            ull acc[2][4];
            #pragma unroll
            for (int p = 0; p < 4; ++p) { acc[0][p] = 0ull; acc[1][p] = 0ull; }

            #pragma unroll 4
            for (int c = 0; c < C; ++c) {
                float a0s = o0p[c], a1s = o1p[c];
                ull a0 = pk2(a0s, a0s), a1 = pk2(a1s, a1s);
                const ull* wp = (const ull*)(sw + c * SW_LD + cg * 8);
                #pragma unroll
                for (int p = 0; p < 4; ++p) {
                    ull w = wp[p];
                    fm2(acc[0][p], a0, w);
                    fm2(acc[1][p], a1, w);
                }
            }

            int cbase = ot * 32 + cg * 8;
            #pragma unroll
            for (int p = 0; p < 4; ++p) {
                float2 bb = *(const float2*)(proj_b + cbase + 2 * p);
                float2 u0 = upk2(acc[0][p]);
                float2 w0 = make_float2(u0.x + bb.x, u0.y + bb.y);
                *(float2*)(ob + rt * C + cbase + 2 * p) = w0;
                if (v1) {
                    float2 u1 = upk2(acc[1][p]);
                    float2 w1 = make_float2(u1.x + bb.x, u1.y + bb.y);
                    *(float2*)(ob + r1 * C + cbase + 2 * p) = w1;
                }
            }
            __syncthreads();
        }
    }
}

extern "C" void kernel_launch(void* const* d_in, const int* in_sizes, int n_in,
                              void* d_out, int out_size)
{
    const float* x          = (const float*)d_in[0];
    const float* qkv_w      = (const float*)d_in[1];
    const float* qkv_b      = (const float*)d_in[2];
    const float* proj_w     = (const float*)d_in[3];
    const float* proj_b     = (const float*)d_in[4];
    const float* bias_table = (const float*)d_in[5];
    const int*   rel_index  = (const int*)d_in[6];
    float* out = (float*)d_out;

    // precompute bias[h][n][m] once per launch (deterministic, graph-capturable)
    bias_prep<<<(H * N * N + 255) / 256, 256>>>(bias_table, rel_index);

    cudaFuncSetAttribute(wa3d_main, cudaFuncAttributeMaxDynamicSharedMemorySize, SMEM_BYTES);
    wa3d_main<<<BN, NT, SMEM_BYTES>>>(x, qkv_w, qkv_b, proj_w, proj_b, out);
}

// round 5
// speedup vs baseline: 1.6497x; 1.6497x over previous
#include <cuda_runtime.h>
#include <cuda_bf16.h>

// Problem constants
#define BN 4096
#define N  98
#define C  96
#define H  3
#define TC 288          // 3*C
#define NT 512          // threads per CTA (16 warps)
#define SCALE 0.17677669529663687f   // 1/sqrt(32)

// Shared-memory strides (floats)
#define SX_LD 97        // x / attention-out rows (odd: conflict-free)
#define SQ_LD 290       // qkv rows (even: v pair loads aligned)
#define SA_LD 99        // probs rows
#define SK_LD 100       // kT rows (even: k pair loads aligned)
#define SW1_LD 146      // GEMM1 weight tile (144 cols + 2 pad, even)
#define SWP_LD 100      // proj weight tile (96 cols + 4 pad, even)

// Region offsets (floats, all even)
#define OFF_SX 0                       // 98*97 = 9506 -> pad 9508
#define OFF_SQ 9508                    // 98*290 = 28420 -> end 37928
#define OFF_UN 37928                   // union: sw1 96*146=14016 | (sa 98*99=9702 + sk 32*100=3200)
#define OFF_SA OFF_UN                  // 9702
#define OFF_SK (OFF_UN + 9702)         // 47630, 3200 -> 50830 (<= 51944)
#define OFF_RI 51944                   // 98
#define SMEM_FLOATS 52044
#define SMEM_BYTES (SMEM_FLOATS * 4)   // 208,176 B

typedef unsigned long long ull;

__device__ float g_bias[H * N * N];    // bias[h][n][m]

// ---- packed f32x2 helpers ----
__device__ __forceinline__ ull pk2(float lo, float hi) {
    ull r; asm("mov.b64 %0,{%1,%2};" : "=l"(r) : "f"(lo), "f"(hi)); return r;
}
__device__ __forceinline__ void fm2(ull& d, ull a, ull b) {
    asm("fma.rn.f32x2 %0,%1,%2,%0;" : "+l"(d) : "l"(a), "l"(b));
}
__device__ __forceinline__ float2 upk2(ull v) {
    float2 r; asm("mov.b64 {%0,%1},%2;" : "=f"(r.x), "=f"(r.y) : "l"(v)); return r;
}

__global__ void bias_prep(const float* __restrict__ table, const int* __restrict__ rel) {
    int i = blockIdx.x * blockDim.x + threadIdx.x;
    if (i < H * N * N) {
        int h = i / (N * N);
        int r = i - h * (N * N);
        g_bias[i] = table[rel[r] * H + h];
    }
}

__global__ void __launch_bounds__(NT, 1)
wa3d_main(const float* __restrict__ x,
          const float* __restrict__ qkv_w, const float* __restrict__ qkv_b,
          const float* __restrict__ proj_w, const float* __restrict__ proj_b,
          float* __restrict__ out)
{
    extern __shared__ float sm[];
    float* sx = sm + OFF_SX;   // x, later attention output [98][97]
    float* sq = sm + OFF_SQ;   // qkv [98][290] (q 0..95, k 96..191, v 192..287)
    float* sa = sm + OFF_SA;   // scores/probs [98][99]
    float* sk = sm + OFF_SK;   // kT [32][100]
    float* sw = sm + OFF_UN;   // weight tiles (union with sa/sk)
    float* ri = sm + OFF_RI;   // 1/rowsum [98]

    const int b   = blockIdx.x;
    const int tid = threadIdx.x;

    // ---- stage x[b] ----
    const float* xb = x + (size_t)b * (N * C);
    for (int i = tid; i < N * C; i += NT) {
        int r = i / C, c = i - r * C;
        sx[r * SX_LD + c] = xb[i];
    }
    __syncthreads();

    // ============ GEMM1: qkv = x @ qkv_w^T + qkv_b  (2 chunks of 144 cols) ============
    for (int ch = 0; ch < 2; ++ch) {
        // stage transposed weight chunk: sw[c][j] = qkv_w[(ch*144+j)*C + c]
        for (int i = tid; i < 144 * C; i += NT) {
            int j = i / C, c = i - j * C;          // coalesced over c
            sw[c * SW1_LD + j] = qkv_w[(ch * 144 + j) * C + c];
        }
        __syncthreads();

        if (tid < 450) {                            // 25 rowgroups(4) x 18 colgroups(8)
            int rg = tid / 18, cgp = tid - rg * 18;
            int r0 = rg * 4, j0 = cgp * 8;
            ull acc[4][4];
            #pragma unroll
            for (int i = 0; i < 4; ++i)
                #pragma unroll
                for (int p = 0; p < 4; ++p) acc[i][p] = 0ull;

            const float* ap = sx + r0 * SX_LD;
            #pragma unroll 4
            for (int c = 0; c < C; ++c) {
                ull a0 = pk2(ap[c], ap[c]);
                ull a1 = pk2(ap[SX_LD + c], ap[SX_LD + c]);
                ull a2 = pk2(ap[2 * SX_LD + c], ap[2 * SX_LD + c]);
                ull a3 = pk2(ap[3 * SX_LD + c], ap[3 * SX_LD + c]);
                const ull* wp = (const ull*)(sw + c * SW1_LD + j0);
                #pragma unroll
                for (int p = 0; p < 4; ++p) {
                    ull w = wp[p];
                    fm2(acc[0][p], a0, w);
                    fm2(acc[1][p], a1, w);
                    fm2(acc[2][p], a2, w);
                    fm2(acc[3][p], a3, w);
                }
            }
            int cb = ch * 144 + j0;
            #pragma unroll
            for (int p = 0; p < 4; ++p) {
                float2 bb = *(const float2*)(qkv_b + cb + 2 * p);
                #pragma unroll
                for (int i = 0; i < 4; ++i) {
                    if (r0 + i < N) {
                        float2 u = upk2(acc[i][p]);
                        sq[(r0 + i) * SQ_LD + cb + 2 * p]     = u.x + bb.x;
                        sq[(r0 + i) * SQ_LD + cb + 2 * p + 1] = u.y + bb.y;
                    }
                }
            }
        }
        __syncthreads();
    }

    // ============ attention per head ============
    const int warp = tid >> 5, lane = tid & 31;
    for (int h = 0; h < H; ++h) {
        // kT[d][m] = k[m][d]
        for (int i = tid; i < 32 * N; i += NT) {
            int d = i / N, m = i - d * N;
            sk[d * SK_LD + m] = sq[m * SQ_LD + C + h * 32 + d];
        }
        __syncthreads();

        // scores: 25 rowgroups(4) x 13 colgroups(8) = 325 tiles
        if (tid < 325) {
            int rg = tid / 13, tm = tid - rg * 13;
            int n0 = rg * 4, m0 = tm * 8;
            ull acc[4][4];
            #pragma unroll
            for (int i = 0; i < 4; ++i)
                #pragma unroll
                for (int p = 0; p < 4; ++p) acc[i][p] = 0ull;

            const float* qp = sq + n0 * SQ_LD + h * 32;
            #pragma unroll 8
            for (int d = 0; d < 32; ++d) {
                ull q0 = pk2(qp[d], qp[d]);
                ull q1 = pk2(qp[SQ_LD + d], qp[SQ_LD + d]);
                ull q2 = pk2(qp[2 * SQ_LD + d], qp[2 * SQ_LD + d]);
                ull q3 = pk2(qp[3 * SQ_LD + d], qp[3 * SQ_LD + d]);
                const ull* kp = (const ull*)(sk + d * SK_LD + m0);
                #pragma unroll
                for (int p = 0; p < 4; ++p) {
                    ull kv = kp[p];
                    fm2(acc[0][p], q0, kv);
                    fm2(acc[1][p], q1, kv);
                    fm2(acc[2][p], q2, kv);
                    fm2(acc[3][p], q3, kv);
                }
            }
            const float* gb = g_bias + (h * N + n0) * N;
            #pragma unroll
            for (int i = 0; i < 4; ++i) {
                if (n0 + i < N) {
                    float* srow = sa + (n0 + i) * SA_LD;
                    const float* gr = gb + i * N;
                    #pragma unroll
                    for (int p = 0; p < 4; ++p) {
                        int m = m0 + 2 * p;
                        float2 u = upk2(acc[i][p]);
                        if (m < N)     srow[m]     = u.x * SCALE + gr[m];
                        if (m + 1 < N) srow[m + 1] = u.y * SCALE + gr[m + 1];
                    }
                }
            }
        }
        __syncthreads();

        // softmax rows (warp per row; N=98 = 3*32 + 2)
        for (int r = warp; r < N; r += 16) {
            float* row = sa + r * SA_LD;
            float v0 = row[lane];
            float va = row[lane + 32];
            float vb = row[lane + 64];
            bool  g3 = (lane < 2);
            float vc = g3 ? row[lane + 96] : -1e30f;
            float mx = fmaxf(fmaxf(v0, va), fmaxf(vb, vc));
            #pragma unroll
            for (int s = 16; s; s >>= 1) mx = fmaxf(mx, __shfl_xor_sync(~0u, mx, s));
            float e0 = __expf(v0 - mx);
            float e1 = __expf(va - mx);
            float e2 = __expf(vb - mx);
            float e3 = g3 ? __expf(vc - mx) : 0.f;
            row[lane] = e0; row[lane + 32] = e1; row[lane + 64] = e2;
            if (g3) row[lane + 96] = e3;
            float s = e0 + e1 + e2 + e3;
            #pragma unroll
            for (int sh = 16; sh; sh >>= 1) s += __shfl_xor_sync(~0u, s, sh);
            if (lane == 0) ri[r] = 1.0f / s;
        }
        __syncthreads();

        // PV: 49 rowgroups(2) x 8 colgroups(4) = 392 tiles
        if (tid < 392) {
            int tn = tid >> 3, td = tid & 7;
            int n0 = tn * 2, d0 = td * 4;
            ull acc[2][2];
            acc[0][0] = acc[0][1] = acc[1][0] = acc[1][1] = 0ull;

            const float* p0 = sa + n0 * SA_LD;
            const float* p1 = p0 + SA_LD;
            const float* vb = sq + 2 * C + h * 32 + d0;
            #pragma unroll 2
            for (int m = 0; m < N; ++m) {
                ull A = pk2(p0[m], p0[m]);
                ull Bq = pk2(p1[m], p1[m]);
                const ull* vp = (const ull*)(vb + m * SQ_LD);
                ull v0 = vp[0], v1 = vp[1];
                fm2(acc[0][0], A, v0);  fm2(acc[0][1], A, v1);
                fm2(acc[1][0], Bq, v0); fm2(acc[1][1], Bq, v1);
            }
            float r0i = ri[n0], r1i = ri[n0 + 1];
            int col = h * 32 + d0;
            #pragma unroll
            for (int p = 0; p < 2; ++p) {
                float2 u0 = upk2(acc[0][p]), u1 = upk2(acc[1][p]);
                sx[n0 * SX_LD + col + 2 * p]           = u0.x * r0i;
                sx[n0 * SX_LD + col + 2 * p + 1]       = u0.y * r0i;
                sx[(n0 + 1) * SX_LD + col + 2 * p]     = u1.x * r1i;
                sx[(n0 + 1) * SX_LD + col + 2 * p + 1] = u1.y * r1i;
            }
        }
        __syncthreads();
    }

    // ============ proj: out = attn_out @ proj_w^T + proj_b ============
    {
        // stage full 96x96 transposed weights
        for (int i = tid; i < C * C; i += NT) {
            int j = i / C, c = i - j * C;
            sw[c * SWP_LD + j] = proj_w[j * C + c];
        }
        __syncthreads();

        if (tid < 300) {                            // 25 rowgroups(4) x 12 colgroups(8)
            int rg = tid / 12, cgp = tid - rg * 12;
            int r0 = rg * 4, j0 = cgp * 8;
            ull acc[4][4];
            #pragma unroll
            for (int i = 0; i < 4; ++i)
                #pragma unroll
                for (int p = 0; p < 4; ++p) acc[i][p] = 0ull;

            const float* ap = sx + r0 * SX_LD;
            #pragma unroll 4
            for (int c = 0; c < C; ++c) {
                ull a0 = pk2(ap[c], ap[c]);
                ull a1 = pk2(ap[SX_LD + c], ap[SX_LD + c]);
                ull a2 = pk2(ap[2 * SX_LD + c], ap[2 * SX_LD + c]);
                ull a3 = pk2(ap[3 * SX_LD + c], ap[3 * SX_LD + c]);
                const ull* wp = (const ull*)(sw + c * SWP_LD + j0);
                #pragma unroll
                for (int p = 0; p < 4; ++p) {
                    ull w = wp[p];
                    fm2(acc[0][p], a0, w);
                    fm2(acc[1][p], a1, w);
                    fm2(acc[2][p], a2, w);
                    fm2(acc[3][p], a3, w);
                }
            }
            float* ob = out + (size_t)b * (N * C);
            #pragma unroll
            for (int p = 0; p < 4; ++p) {
                float2 bb = *(const float2*)(proj_b + j0 + 2 * p);
                #pragma unroll
                for (int i = 0; i < 4; ++i) {
                    if (r0 + i < N) {
                        float2 u = upk2(acc[i][p]);
                        float2 w2 = make_float2(u.x + bb.x, u.y + bb.y);
                        *(float2*)(ob + (r0 + i) * C + j0 + 2 * p) = w2;
                    }
                }
            }
        }
    }
}

extern "C" void kernel_launch(void* const* d_in, const int* in_sizes, int n_in,
                              void* d_out, int out_size)
{
    const float* x          = (const float*)d_in[0];
    const float* qkv_w      = (const float*)d_in[1];
    const float* qkv_b      = (const float*)d_in[2];
    const float* proj_w     = (const float*)d_in[3];
    const float* proj_b     = (const float*)d_in[4];
    const float* bias_table = (const float*)d_in[5];
    const int*   rel_index  = (const int*)d_in[6];
    float* out = (float*)d_out;

    bias_prep<<<(H * N * N + 255) / 256, 256>>>(bias_table, rel_index);

    cudaFuncSetAttribute(wa3d_main, cudaFuncAttributeMaxDynamicSharedMemorySize, SMEM_BYTES);
    wa3d_main<<<BN, NT, SMEM_BYTES>>>(x, qkv_w, qkv_b, proj_w, proj_b, out);
}

// round 7
// speedup vs baseline: 2.2194x; 1.3454x over previous
#include <cuda_runtime.h>

#define NT 512
#define SCALEF 0.17677669529663687f   // 1/sqrt(32)

// smem strides (floats) — chosen so per-warp row sets map to distinct banks
#define SX_LD 102   // 102%32=6 -> 6n distinct for 16 consecutive rows; even (f2 ok)
#define SQK_LD 194  // 194%32=2 -> 2n distinct for 16 rows; even
#define SV_LD 100   // mult of 4 (f4 aligned); same-row vector loads conflict-free
#define SA_LD 100   // mult of 4; 4n distinct for 8 consecutive rows
#define SK_LD 128   // padded k-transpose rows (cols 98..127 zero-filled)
#define SW_LD 100   // proj weight tile rows (96 + 4 pad)

// region offsets (floats)
#define OFF_SX   0        // 98*102 = 9996
#define OFF_SQK  10000    // 98*194 = 19012
#define OFF_SV   29016    // 98*100 = 9800
#define OFF_SA   38816    // 98*100 = 9800   (union with proj weight tile 96*100=9600)
#define OFF_SW   38816
#define OFF_SK   48616    // 32*128 = 4096
#define OFF_RI   52712    // 98
#define SMEM_FLOATS 52812
#define SMEM_BYTES (SMEM_FLOATS * 4)   // 211,248 B

typedef unsigned long long ull;

__device__ float g_wqkvT[96 * 288];   // wT[c][j] = qkv_w[j*96+c]
__device__ float g_wprojT[96 * 96];   // wT[c][j] = proj_w[j*96+c]
__device__ float g_bias[3 * 98 * 100]; // bias[h][n][m], m-padded to 100 (pad = 0)

// ---- packed f32x2 helpers ----
__device__ __forceinline__ ull pk2(float lo, float hi) {
    ull r; asm("mov.b64 %0,{%1,%2};" : "=l"(r) : "f"(lo), "f"(hi)); return r;
}
__device__ __forceinline__ void fm2(ull& d, ull a, ull b) {
    asm("fma.rn.f32x2 %0,%1,%2,%0;" : "+l"(d) : "l"(a), "l"(b));
}
__device__ __forceinline__ float2 upk2(ull v) {
    float2 r; asm("mov.b64 {%0,%1},%2;" : "=f"(r.x), "=f"(r.y) : "l"(v)); return r;
}

// ---- prep: transposed weights + padded bias, once per launch ----
__global__ void prep_kernel(const float* __restrict__ qkv_w,
                            const float* __restrict__ proj_w,
                            const float* __restrict__ table,
                            const int* __restrict__ rel)
{
    int i = blockIdx.x * blockDim.x + threadIdx.x;
    if (i < 96 * 288) {
        int c = i / 288, j = i - c * 288;
        g_wqkvT[i] = qkv_w[j * 96 + c];
    } else if (i < 96 * 288 + 96 * 96) {
        int k = i - 96 * 288;
        int c = k / 96, j = k - c * 96;
        g_wprojT[k] = proj_w[j * 96 + c];
    } else if (i < 96 * 288 + 96 * 96 + 3 * 98 * 100) {
        int k = i - (96 * 288 + 96 * 96);
        int h = k / 9800, r = k - h * 9800;
        int n = r / 100, m = r - n * 100;
        g_bias[k] = (m < 98) ? table[rel[n * 98 + m] * 3 + h] : 0.f;
    }
}

__global__ void __launch_bounds__(NT, 1)
wa3d_main(const float* __restrict__ x,
          const float* __restrict__ qkv_b,
          const float* __restrict__ proj_b,
          float* __restrict__ out)
{
    extern __shared__ float sm[];
    float* sx  = sm + OFF_SX;    // x, later attention output [98][102]
    float* sqk = sm + OFF_SQK;   // q|k [98][194] (q 0..95, k 96..191)
    float* sv  = sm + OFF_SV;    // v [98][100]
    float* sa  = sm + OFF_SA;    // scores/probs [98][100]
    float* sw  = sm + OFF_SW;    // proj weight tile (union with sa)
    float* sk  = sm + OFF_SK;    // kT [32][128], cols>=98 zero
    float* ri  = sm + OFF_RI;    // 1/rowsum [98]

    const int b    = blockIdx.x;
    const int tid  = threadIdx.x;
    const int warp = tid >> 5, lane = tid & 31;
    const int tr   = lane >> 3;          // 0..3
    const int tc   = lane & 7;           // 0..7

    // ---- stage x[b] ----
    const float* xb = x + (size_t)b * 9408;
    for (int i = tid; i < 9408; i += NT) {
        int r = i / 96, c = i - r * 96;
        sx[r * SX_LD + c] = xb[i];
    }
    __syncthreads();

    // ============ GEMM1: qkv = x @ qkv_w^T + b  (63 warp-tiles of 16x32) ============
    for (int t = warp; t < 63; t += 16) {
        int tileR = t / 9, tileC = t - tileR * 9;
        int n0 = tileR * 16 + tr * 4;
        int j0 = tileC * 32 + tc * 4;
        const float* a0 = sx + min(n0,     97) * SX_LD;
        const float* a1 = sx + min(n0 + 1, 97) * SX_LD;
        const float* a2 = sx + min(n0 + 2, 97) * SX_LD;
        const float* a3 = sx + min(n0 + 3, 97) * SX_LD;
        const float* wb = g_wqkvT + j0;

        ull acc[4][2];
        #pragma unroll
        for (int i = 0; i < 4; ++i) { acc[i][0] = 0ull; acc[i][1] = 0ull; }

        #pragma unroll 4
        for (int c = 0; c < 96; c += 2) {
            float2 v0 = *(const float2*)(a0 + c);
            float2 v1 = *(const float2*)(a1 + c);
            float2 v2 = *(const float2*)(a2 + c);
            float2 v3 = *(const float2*)(a3 + c);
            ulonglong2 wA = __ldg((const ulonglong2*)(wb + (size_t)c * 288));
            ulonglong2 wB = __ldg((const ulonglong2*)(wb + (size_t)(c + 1) * 288));
            ull t0;
            t0 = pk2(v0.x, v0.x); fm2(acc[0][0], t0, wA.x); fm2(acc[0][1], t0, wA.y);
            t0 = pk2(v0.y, v0.y); fm2(acc[0][0], t0, wB.x); fm2(acc[0][1], t0, wB.y);
            t0 = pk2(v1.x, v1.x); fm2(acc[1][0], t0, wA.x); fm2(acc[1][1], t0, wA.y);
            t0 = pk2(v1.y, v1.y); fm2(acc[1][0], t0, wB.x); fm2(acc[1][1], t0, wB.y);
            t0 = pk2(v2.x, v2.x); fm2(acc[2][0], t0, wA.x); fm2(acc[2][1], t0, wA.y);
            t0 = pk2(v2.y, v2.y); fm2(acc[2][0], t0, wB.x); fm2(acc[2][1], t0, wB.y);
            t0 = pk2(v3.x, v3.x); fm2(acc[3][0], t0, wA.x); fm2(acc[3][1], t0, wA.y);
            t0 = pk2(v3.y, v3.y); fm2(acc[3][0], t0, wB.x); fm2(acc[3][1], t0, wB.y);
        }

        float4 bb = *(const float4*)(qkv_b + j0);
        #pragma unroll
        for (int i = 0; i < 4; ++i) {
            int n = n0 + i;
            if (n < 98) {
                float2 u0 = upk2(acc[i][0]), u1 = upk2(acc[i][1]);
                float r0 = u0.x + bb.x, r1 = u0.y + bb.y;
                float r2 = u1.x + bb.z, r3 = u1.y + bb.w;
                if (j0 < 192) {
                    float* d = sqk + n * SQK_LD + j0;
                    d[0] = r0; d[1] = r1; d[2] = r2; d[3] = r3;
                } else {
                    *(float4*)(sv + n * SV_LD + (j0 - 192)) = make_float4(r0, r1, r2, r3);
                }
            }
        }
    }
    __syncthreads();

    // ============ attention per head ============
    for (int h = 0; h < 3; ++h) {
        // kT fill, zero-padded cols 98..127
        for (int i = tid; i < 32 * 128; i += NT) {
            int d = i >> 7, m = i & 127;
            sk[i] = (m < 98) ? sqk[m * SQK_LD + 96 + h * 32 + d] : 0.f;
        }
        __syncthreads();

        // ---- scores: 28 warp-tiles of 16x32 ----
        for (int t = warp; t < 28; t += 16) {
            int tileR = t >> 2, tileC = t & 3;
            int n0 = tileR * 16 + tr * 4;
            int m0 = tileC * 32 + tc * 4;       // <= 124, in-bounds of padded sk
            const float* q0 = sqk + min(n0,     97) * SQK_LD + h * 32;
            const float* q1 = sqk + min(n0 + 1, 97) * SQK_LD + h * 32;
            const float* q2 = sqk + min(n0 + 2, 97) * SQK_LD + h * 32;
            const float* q3 = sqk + min(n0 + 3, 97) * SQK_LD + h * 32;
            const float* kb = sk + m0;

            ull acc[4][2];
            #pragma unroll
            for (int i = 0; i < 4; ++i) { acc[i][0] = 0ull; acc[i][1] = 0ull; }

            #pragma unroll 4
            for (int d = 0; d < 32; d += 2) {
                float2 v0 = *(const float2*)(q0 + d);
                float2 v1 = *(const float2*)(q1 + d);
                float2 v2 = *(const float2*)(q2 + d);
                float2 v3 = *(const float2*)(q3 + d);
                ulonglong2 kA = *(const ulonglong2*)(kb + d * SK_LD);
                ulonglong2 kB = *(const ulonglong2*)(kb + (d + 1) * SK_LD);
                ull t0;
                t0 = pk2(v0.x, v0.x); fm2(acc[0][0], t0, kA.x); fm2(acc[0][1], t0, kA.y);
                t0 = pk2(v0.y, v0.y); fm2(acc[0][0], t0, kB.x); fm2(acc[0][1], t0, kB.y);
                t0 = pk2(v1.x, v1.x); fm2(acc[1][0], t0, kA.x); fm2(acc[1][1], t0, kA.y);
                t0 = pk2(v1.y, v1.y); fm2(acc[1][0], t0, kB.x); fm2(acc[1][1], t0, kB.y);
                t0 = pk2(v2.x, v2.x); fm2(acc[2][0], t0, kA.x); fm2(acc[2][1], t0, kA.y);
                t0 = pk2(v2.y, v2.y); fm2(acc[2][0], t0, kB.x); fm2(acc[2][1], t0, kB.y);
                t0 = pk2(v3.x, v3.x); fm2(acc[3][0], t0, kA.x); fm2(acc[3][1], t0, kA.y);
                t0 = pk2(v3.y, v3.y); fm2(acc[3][0], t0, kB.x); fm2(acc[3][1], t0, kB.y);
            }

            const float* gb = g_bias + h * 9800 + min(m0, 96);
            #pragma unroll
            for (int i = 0; i < 4; ++i) {
                int n = n0 + i;
                if (n < 98) {
                    float4 bv = __ldg((const float4*)(gb + n * 100));
                    float2 u0 = upk2(acc[i][0]), u1 = upk2(acc[i][1]);
                    float s0 = u0.x * SCALEF + bv.x, s1 = u0.y * SCALEF + bv.y;
                    float s2 = u1.x * SCALEF + bv.z, s3 = u1.y * SCALEF + bv.w;
                    if (m0 < 96) {
                        *(float4*)(sa + n * SA_LD + m0) = make_float4(s0, s1, s2, s3);
                    } else if (m0 == 96) {
                        sa[n * SA_LD + 96] = s0;
                        sa[n * SA_LD + 97] = s1;
                    }
                }
            }
        }
        __syncthreads();

        // ---- softmax (warp per row) ----
        for (int r = warp; r < 98; r += 16) {
            float* row = sa + r * SA_LD;
            float v0 = row[lane];
            float va = row[lane + 32];
            float vb = row[lane + 64];
            bool  g3 = (lane < 2);
            float vc = g3 ? row[lane + 96] : -1e30f;
            float mx = fmaxf(fmaxf(v0, va), fmaxf(vb, vc));
            #pragma unroll
            for (int s = 16; s; s >>= 1) mx = fmaxf(mx, __shfl_xor_sync(~0u, mx, s));
            float e0 = __expf(v0 - mx);
            float e1 = __expf(va - mx);
            float e2 = __expf(vb - mx);
            float e3 = g3 ? __expf(vc - mx) : 0.f;
            row[lane] = e0; row[lane + 32] = e1; row[lane + 64] = e2;
            if (g3) row[lane + 96] = e3;
            float s = e0 + e1 + e2 + e3;
            #pragma unroll
            for (int sh = 16; sh; sh >>= 1) s += __shfl_xor_sync(~0u, s, sh);
            if (lane == 0) ri[r] = 1.0f / s;
        }
        __syncthreads();

        // ---- PV: 13 warp-tiles of 8x32, thread 2x4 ----
        if (warp < 13) {
            int n0 = warp * 8 + tr * 2;
            int na = min(n0, 97), nb = min(n0 + 1, 97);
            int d0 = tc * 4;
            const float* pa = sa + na * SA_LD;
            const float* pb = sa + nb * SA_LD;
            const float* vbase = sv + h * 32 + d0;

            ull aA0 = 0, aA1 = 0, aB0 = 0, aB1 = 0;
            #pragma unroll 4
            for (int m = 0; m < 96; m += 4) {
                float p0a[4], p1a[4];
                *(float4*)p0a = *(const float4*)(pa + m);
                *(float4*)p1a = *(const float4*)(pb + m);
                #pragma unroll
                for (int mm = 0; mm < 4; ++mm) {
                    ulonglong2 vv = *(const ulonglong2*)(vbase + (m + mm) * SV_LD);
                    ull ta = pk2(p0a[mm], p0a[mm]);
                    fm2(aA0, ta, vv.x); fm2(aA1, ta, vv.y);
                    ull tb = pk2(p1a[mm], p1a[mm]);
                    fm2(aB0, tb, vv.x); fm2(aB1, tb, vv.y);
                }
            }
            {   // tail m = 96, 97
                float2 p0t = *(const float2*)(pa + 96);
                float2 p1t = *(const float2*)(pb + 96);
                ulonglong2 v96 = *(const ulonglong2*)(vbase + 96 * SV_LD);
                ulonglong2 v97 = *(const ulonglong2*)(vbase + 97 * SV_LD);
                ull ta = pk2(p0t.x, p0t.x); fm2(aA0, ta, v96.x); fm2(aA1, ta, v96.y);
                ta = pk2(p0t.y, p0t.y);     fm2(aA0, ta, v97.x); fm2(aA1, ta, v97.y);
                ull tb = pk2(p1t.x, p1t.x); fm2(aB0, tb, v96.x); fm2(aB1, tb, v96.y);
                tb = pk2(p1t.y, p1t.y);     fm2(aB0, tb, v97.x); fm2(aB1, tb, v97.y);
            }
            float ra = ri[na], rb = ri[nb];
            int col = h * 32 + d0;
            if (n0 < 98) {
                float2 u0 = upk2(aA0), u1 = upk2(aA1);
                float* d = sx + n0 * SX_LD + col;
                d[0] = u0.x * ra; d[1] = u0.y * ra; d[2] = u1.x * ra; d[3] = u1.y * ra;
            }
            if (n0 + 1 < 98) {
                float2 u0 = upk2(aB0), u1 = upk2(aB1);
                float* d = sx + (n0 + 1) * SX_LD + col;
                d[0] = u0.x * rb; d[1] = u0.y * rb; d[2] = u1.x * rb; d[3] = u1.y * rb;
            }
        }
        __syncthreads();
    }

    // ============ proj: out = attn_out @ proj_w^T + b ============
    // stage transposed proj weights (overlays sa, dead now)
    for (int i = tid; i < 96 * 96; i += NT) {
        int c = i / 96, j = i - c * 96;
        sw[c * SW_LD + j] = g_wprojT[i];
    }
    __syncthreads();

    float* ob = out + (size_t)b * 9408;
    for (int t = warp; t < 39; t += 16) {
        int tileR = t / 3, tileC = t - tileR * 3;
        int n0 = tileR * 8 + tr * 2;
        int na = min(n0, 97), nb = min(n0 + 1, 97);
        int j0 = tileC * 32 + tc * 4;
        const float* a0 = sx + na * SX_LD;
        const float* a1 = sx + nb * SX_LD;
        const float* wb = sw + j0;

        ull aA0 = 0, aA1 = 0, aB0 = 0, aB1 = 0;
        #pragma unroll 4
        for (int c = 0; c < 96; c += 2) {
            float2 qa = *(const float2*)(a0 + c);
            float2 qb = *(const float2*)(a1 + c);
            ulonglong2 wA = *(const ulonglong2*)(wb + c * SW_LD);
            ulonglong2 wB = *(const ulonglong2*)(wb + (c + 1) * SW_LD);
            ull t0;
            t0 = pk2(qa.x, qa.x); fm2(aA0, t0, wA.x); fm2(aA1, t0, wA.y);
            t0 = pk2(qa.y, qa.y); fm2(aA0, t0, wB.x); fm2(aA1, t0, wB.y);
            t0 = pk2(qb.x, qb.x); fm2(aB0, t0, wA.x); fm2(aB1, t0, wA.y);
            t0 = pk2(qb.y, qb.y); fm2(aB0, t0, wB.x); fm2(aB1, t0, wB.y);
        }
        float4 bb = *(const float4*)(proj_b + j0);
        if (n0 < 98) {
            float2 u0 = upk2(aA0), u1 = upk2(aA1);
            *(float4*)(ob + n0 * 96 + j0) =
                make_float4(u0.x + bb.x, u0.y + bb.y, u1.x + bb.z, u1.y + bb.w);
        }
        if (n0 + 1 < 98) {
            float2 u0 = upk2(aB0), u1 = upk2(aB1);
            *(float4*)(ob + (n0 + 1) * 96 + j0) =
                make_float4(u0.x + bb.x, u0.y + bb.y, u1.x + bb.z, u1.y + bb.w);
        }
    }
}

extern "C" void kernel_launch(void* const* d_in, const int* in_sizes, int n_in,
                              void* d_out, int out_size)
{
    const float* x          = (const float*)d_in[0];
    const float* qkv_w      = (const float*)d_in[1];
    const float* qkv_b      = (const float*)d_in[2];
    const float* proj_w     = (const float*)d_in[3];
    const float* proj_b     = (const float*)d_in[4];
    const float* bias_table = (const float*)d_in[5];
    const int*   rel_index  = (const int*)d_in[6];
    float* out = (float*)d_out;

    int prep_total = 96 * 288 + 96 * 96 + 3 * 98 * 100;
    prep_kernel<<<(prep_total + 255) / 256, 256>>>(qkv_w, proj_w, bias_table, rel_index);

    cudaFuncSetAttribute(wa3d_main, cudaFuncAttributeMaxDynamicSharedMemorySize, SMEM_BYTES);
    wa3d_main<<<4096, NT, SMEM_BYTES>>>(x, qkv_b, proj_b, out);
}